// round 15
// baseline (speedup 1.0000x reference)
#include <cuda_runtime.h>
#include <cuda_bf16.h>

#define NBINS   2200
#define NCHAN   12
#define NBATCH  32
#define PLANE   65536            // 256*256
#define SPLIT   2                // blocks per (batch, channel) plane
#define THREADS 256
#define ELEMS_PER_BLOCK (PLANE / SPLIT)   // 32768 floats per block
#define N4      (ELEMS_PER_BLOCK / 4)     // 8192 float4 per block

__device__ __forceinline__ void bin1(float f, int* sh) {
    if (f >= -1200.0f && f <= 1000.0f) {
        int idx = __float2int_rd(f + 1200.0f);
        atomicAdd(&sh[min(idx, NBINS - 1)], 1);
    }
}

__global__ __launch_bounds__(THREADS)
void hist_kernel(const float* __restrict__ x, float* __restrict__ out) {
    __shared__ int sh[NBINS];
    for (int i = threadIdx.x; i < NBINS; i += THREADS) sh[i] = 0;
    __syncthreads();

    const int block = blockIdx.x;          // 0 .. NBATCH*NCHAN*SPLIT-1
    const int plane = block / SPLIT;       // b * NCHAN + c  (B,C,H,W layout)
    const int part  = block % SPLIT;
    const int chan  = plane % NCHAN;

    const float4* __restrict__ p = reinterpret_cast<const float4*>(
        x + (size_t)plane * PLANE + (size_t)part * ELEMS_PER_BLOCK);

    // 8192 float4 / 256 threads = 32 per thread; process 2 per iteration,
    // front-batched loads for MLP.
    #pragma unroll 4
    for (int i = threadIdx.x; i < N4; i += 2 * THREADS) {
        float4 a = p[i];
        float4 b = p[i + THREADS];
        bin1(a.x, sh); bin1(a.y, sh); bin1(a.z, sh); bin1(a.w, sh);
        bin1(b.x, sh); bin1(b.y, sh); bin1(b.z, sh); bin1(b.w, sh);
    }
    __syncthreads();

    // Flush shared counts as exact float REDs directly into the output.
    float* __restrict__ g = out + chan * NBINS;
    for (int i = threadIdx.x; i < NBINS; i += THREADS) {
        int v = sh[i];
        if (v) atomicAdd(&g[i], (float)v);
    }
}

extern "C" void kernel_launch(void* const* d_in, const int* in_sizes, int n_in,
                              void* d_out, int out_size) {
    const float* x    = (const float*)d_in[0];       // [32,12,256,256] fp32
    const float* hist = (const float*)d_in[1];       // [12,2200] fp32
    float* out        = (float*)d_out;               // [12,2200] fp32

    // out = hist_counts via async D2D copy node (graph-capturable, no
    // kernel launch), stream-ordered before the hist kernel's atomics.
    cudaMemcpyAsync(out, hist, (size_t)NCHAN * NBINS * sizeof(float),
                    cudaMemcpyDeviceToDevice, 0);
    hist_kernel<<<NBATCH * NCHAN * SPLIT, THREADS>>>(x, out);
}

// round 16
// speedup vs baseline: 1.1006x; 1.1006x over previous
#include <cuda_runtime.h>
#include <cuda_bf16.h>

#define NBINS   2200
#define NCHAN   12
#define NBATCH  32
#define PLANE   65536            // 256*256
#define SPLIT   2                // blocks per (batch, channel) plane
#define THREADS 256
#define ELEMS_PER_BLOCK (PLANE / SPLIT)   // 32768 floats per block
#define N4      (ELEMS_PER_BLOCK / 4)     // 8192 float4 per block

// out = hist_counts (init before atomics; out is poisoned by harness)
__global__ void init_out_kernel(const float4* __restrict__ hist_in,
                                float4* __restrict__ out) {
    int i = blockIdx.x * blockDim.x + threadIdx.x;
    if (i < (NCHAN * NBINS) / 4) out[i] = hist_in[i];
}

__device__ __forceinline__ void bin1(float f, int* sh) {
    if (f >= -1200.0f && f <= 1000.0f) {
        int idx = __float2int_rd(f + 1200.0f);
        atomicAdd(&sh[min(idx, NBINS - 1)], 1);
    }
}

__global__ __launch_bounds__(THREADS)
void hist_kernel(const float* __restrict__ x, float* __restrict__ out) {
    __shared__ int sh[NBINS];
    for (int i = threadIdx.x; i < NBINS; i += THREADS) sh[i] = 0;
    __syncthreads();

    const int block = blockIdx.x;          // 0 .. NBATCH*NCHAN*SPLIT-1
    const int plane = block / SPLIT;       // b * NCHAN + c  (B,C,H,W layout)
    const int part  = block % SPLIT;
    const int chan  = plane % NCHAN;

    const float4* __restrict__ p = reinterpret_cast<const float4*>(
        x + (size_t)plane * PLANE + (size_t)part * ELEMS_PER_BLOCK);

    // 8192 float4 / 256 threads = 32 per thread; process 2 per iteration,
    // front-batched loads for MLP.
    #pragma unroll 4
    for (int i = threadIdx.x; i < N4; i += 2 * THREADS) {
        float4 a = p[i];
        float4 b = p[i + THREADS];
        bin1(a.x, sh); bin1(a.y, sh); bin1(a.z, sh); bin1(a.w, sh);
        bin1(b.x, sh); bin1(b.y, sh); bin1(b.z, sh); bin1(b.w, sh);
    }
    __syncthreads();

    // Flush shared counts as exact float REDs directly into the output.
    float* __restrict__ g = out + chan * NBINS;
    for (int i = threadIdx.x; i < NBINS; i += THREADS) {
        int v = sh[i];
        if (v) atomicAdd(&g[i], (float)v);
    }
}

extern "C" void kernel_launch(void* const* d_in, const int* in_sizes, int n_in,
                              void* d_out, int out_size) {
    const float* x    = (const float*)d_in[0];       // [32,12,256,256] fp32
    const float* hist = (const float*)d_in[1];       // [12,2200] fp32
    float* out        = (float*)d_out;               // [12,2200] fp32

    const int n4 = (NCHAN * NBINS) / 4;              // 6600
    init_out_kernel<<<(n4 + 255) / 256, 256>>>((const float4*)hist, (float4*)out);
    hist_kernel<<<NBATCH * NCHAN * SPLIT, THREADS>>>(x, out);
}